// round 4
// baseline (speedup 1.0000x reference)
#include <cuda_runtime.h>

// NT-Xent loss. inp: (C=8, V=2, B=4096, D=512) fp32.
// Warp-per-b. Per-warp private 3-deep cp.async ring of 8KB stages
// (16 rows x 128 d). Lane l copies chunk l of every row and reads only its
// own chunks -> no smem sync of any kind in the mainloop.
// Gram G[8][16] in registers via f32x2 FMA (k-paired, acc2[i*8+k2]).
// Even norms = Gram diagonal; odd-row sumsq fused.
// Butterfly fold -> lane L owns G[L>>2][4*(L&3)+m]; in-warp LSE epilogue.

static constexpr int      kB     = 4096;
static constexpr unsigned FULL   = 0xffffffffu;
static constexpr int      kStage = 8192;              // 16 rows * 128 floats * 4B
static constexpr int      kRing  = 3;
static constexpr int      kSmem  = 4 * kRing * kStage; // 96 KB / CTA
static constexpr size_t   kRowB  = 4096ull * 512ull * 4ull;  // 8 MB row stride (bytes)

__device__ float    g_partials[kB];
__device__ unsigned g_ticket;   // zero-init; reset by last CTA every launch

__device__ __forceinline__ unsigned long long pack2(float lo, float hi) {
    unsigned long long r;
    asm("mov.b64 %0, {%1, %2};" : "=l"(r) : "f"(lo), "f"(hi));
    return r;
}
__device__ __forceinline__ void unpack2(unsigned long long v, float& lo, float& hi) {
    asm("mov.b64 {%0, %1}, %2;" : "=f"(lo), "=f"(hi) : "l"(v));
}
__device__ __forceinline__ void ffma2(unsigned long long& acc,
                                      unsigned long long a, unsigned long long b) {
    asm("fma.rn.f32x2 %0, %1, %2, %0;" : "+l"(acc) : "l"(a), "l"(b));
}
__device__ __forceinline__ float elem(const float4& v, int d) {
    return d == 0 ? v.x : d == 1 ? v.y : d == 2 ? v.z : v.w;
}

__global__ void __launch_bounds__(128)
ntxent(const float* __restrict__ inp, float* __restrict__ out)
{
    __shared__ float    snorm[4][16];
    __shared__ float    sred[4];
    __shared__ unsigned sFlag;
    extern __shared__ char dynbuf[];

    const int tid  = threadIdx.x;
    const int w    = tid >> 5;
    const int lane = tid & 31;
    const int b    = blockIdx.x * 4 + w;

    char* mybuf = dynbuf + w * (kRing * kStage);
    const unsigned sdl  = (unsigned)__cvta_generic_to_shared(mybuf) + lane * 16;
    const char*    gsrc = (const char*)(inp + (size_t)b * 512 + lane * 4);

    unsigned long long acc2[64];   // acc2[i*8+k2] = (G[i][2k2], G[i][2k2+1])
    unsigned long long ss2[8];     // odd-row sumsq, d-paired
    #pragma unroll
    for (int q = 0; q < 64; q++) acc2[q] = 0ull;
    #pragma unroll
    for (int q = 0; q < 8; q++)  ss2[q] = 0ull;

    // ---- stage issue: 16 rows x 16B per lane, one commit group ----
    auto issue = [&](int gs, int rs) {
        #pragma unroll
        for (int j = 0; j < 16; j++)
            asm volatile("cp.async.cg.shared.global [%0], [%1], 16;"
                         :: "r"(sdl + rs * kStage + j * 512),
                            "l"(gsrc + (size_t)j * kRowB + gs * 512));
        asm volatile("cp.async.commit_group;" ::: "memory");
    };

    // ---- stage compute: lane-private chunks only ----
    auto compute = [&](int rs) {
        const float4* base = reinterpret_cast<const float4*>(mybuf + rs * kStage) + lane;
        float4 xa[8], xo[8];                       // even rows (= anchors) / odd rows
        #pragma unroll
        for (int p = 0; p < 8; p++) {
            xa[p] = base[(2 * p) * 32];
            xo[p] = base[(2 * p + 1) * 32];
        }
        #pragma unroll
        for (int d = 0; d < 4; d++) {
            unsigned long long xp[8];
            #pragma unroll
            for (int k2 = 0; k2 < 8; k2++)
                xp[k2] = pack2(elem(xa[k2], d), elem(xo[k2], d));   // cols (2k2, 2k2+1)
            #pragma unroll
            for (int i = 0; i < 8; i++) {
                const float av = elem(xa[i], d);                    // anchor row 2i
                const unsigned long long ad = pack2(av, av);
                #pragma unroll
                for (int k2 = 0; k2 < 8; k2++)
                    ffma2(acc2[i * 8 + k2], ad, xp[k2]);
            }
        }
        #pragma unroll
        for (int p = 0; p < 8; p++) {
            const unsigned long long h0 = pack2(xo[p].x, xo[p].y);
            const unsigned long long h1 = pack2(xo[p].z, xo[p].w);
            ffma2(ss2[p], h0, h0);
            ffma2(ss2[p], h1, h1);
        }
    };

    // ---- 4-stage pipeline, 3-deep prefetch ----
    issue(0, 0); issue(1, 1); issue(2, 2);
    asm volatile("cp.async.wait_group 2;" ::: "memory");
    compute(0);
    issue(3, 0);
    asm volatile("cp.async.wait_group 2;" ::: "memory");
    compute(1);
    asm volatile("cp.async.wait_group 1;" ::: "memory");
    compute(2);
    asm volatile("cp.async.wait_group 0;" ::: "memory");
    compute(0);

    // ---- unpack to 128 scalars ----
    float a[128];
    #pragma unroll
    for (int i = 0; i < 8; i++)
        #pragma unroll
        for (int k2 = 0; k2 < 8; k2++)
            unpack2(acc2[i * 8 + k2], a[i * 16 + 2 * k2], a[i * 16 + 2 * k2 + 1]);

    // ---- folded butterfly: lane L owns G[L>>2][4*(L&3)+m] ----
    #pragma unroll
    for (int s = 0; s < 5; s++) {
        const int  off = 16 >> s;
        const int  n   = 64 >> s;
        const bool hi  = (lane & off) != 0;
        #pragma unroll
        for (int m = 0; m < n; m++) {
            const float mine = hi ? a[m + n] : a[m];
            const float send = hi ? a[m]     : a[m + n];
            a[m] = mine + __shfl_xor_sync(FULL, send, off);
        }
    }

    // ---- odd-row sumsq reduce: lane L -> ||row 2*(L>>2)+1||^2 ----
    float sv[8];
    #pragma unroll
    for (int p = 0; p < 8; p++) { float lo, hi2; unpack2(ss2[p], lo, hi2); sv[p] = lo + hi2; }
    #pragma unroll
    for (int s = 0; s < 3; s++) {
        const int  off = 16 >> s;
        const int  n   = 4 >> s;
        const bool hi  = (lane & off) != 0;
        #pragma unroll
        for (int m = 0; m < n; m++) {
            const float mine = hi ? sv[m + n] : sv[m];
            const float send = hi ? sv[m]     : sv[m + n];
            sv[m] = mine + __shfl_xor_sync(FULL, send, off);
        }
    }
    float ssodd = sv[0];
    ssodd += __shfl_xor_sync(FULL, ssodd, 2);
    ssodd += __shfl_xor_sync(FULL, ssodd, 1);

    // ---- stage 16 squared norms in per-warp smem ----
    const int i = lane >> 2;
    if ((lane & 3) == 0) snorm[w][2 * i + 1] = ssodd;            // odd rows
    #pragma unroll
    for (int m = 0; m < 4; m++) {                                 // even rows: Gram diag
        const int j = 4 * lane + m;                               // j = i*16 + k
        if ((j & 15) == 2 * (j >> 4)) snorm[w][j & 15] = a[m];
    }
    __syncwarp();

    // ---- LSE epilogue, in-warp ----
    const float inva  = 1.0f / fmaxf(sqrtf(snorm[w][2 * i]), 1e-12f);
    const int   kbase = (lane & 3) * 4;
    float sim[4];
    bool  val[4];
    float mx = -3.0e38f;
    #pragma unroll
    for (int m = 0; m < 4; m++) {
        const int   k    = kbase + m;
        const float invk = 1.0f / fmaxf(sqrtf(snorm[w][k]), 1e-12f);
        sim[m] = a[m] * inva * invk * 10.0f;
        val[m] = ((k >> 1) != i) || (k == 2 * i + 1);
        if (val[m]) mx = fmaxf(mx, sim[m]);
    }
    mx = fmaxf(mx, __shfl_xor_sync(FULL, mx, 1));
    mx = fmaxf(mx, __shfl_xor_sync(FULL, mx, 2));
    float sum = 0.f;
    #pragma unroll
    for (int m = 0; m < 4; m++)
        if (val[m]) sum += __expf(sim[m] - mx);
    sum += __shfl_xor_sync(FULL, sum, 1);
    sum += __shfl_xor_sync(FULL, sum, 2);

    float contrib = 0.f;
    #pragma unroll
    for (int m = 0; m < 4; m++)
        if (kbase + m == 2 * i + 1)                   // this sim is the positive
            contrib = (mx + __logf(sum)) - sim[m];
    #pragma unroll
    for (int off = 16; off > 0; off >>= 1)
        contrib += __shfl_xor_sync(FULL, contrib, off);
    if (lane == 0) g_partials[b] = contrib;

    // ---- deterministic fused finish ----
    __syncthreads();
    if (tid == 0) {
        __threadfence();
        const unsigned tk = atomicAdd(&g_ticket, 1u);
        sFlag = (tk == gridDim.x - 1) ? 1u : 0u;
    }
    __syncthreads();
    if (sFlag) {
        float s = 0.f;
        #pragma unroll
        for (int m = 0; m < kB / 128; m++)
            s += __ldcg(&g_partials[tid + m * 128]);   // fixed order: deterministic
        #pragma unroll
        for (int off = 16; off > 0; off >>= 1)
            s += __shfl_xor_sync(FULL, s, off);
        if (lane == 0) sred[w] = s;
        __syncthreads();
        if (tid == 0) {
            out[0] = (sred[0] + sred[1] + sred[2] + sred[3]) * (1.0f / (8.0f * 4096.0f));
            g_ticket = 0u;   // reset for next graph replay
        }
    }
}

extern "C" void kernel_launch(void* const* d_in, const int* in_sizes, int n_in,
                              void* d_out, int out_size) {
    (void)in_sizes; (void)n_in; (void)out_size;
    const float* inp = (const float*)d_in[0];
    cudaFuncSetAttribute(ntxent, cudaFuncAttributeMaxDynamicSharedMemorySize, kSmem);
    ntxent<<<kB / 4, 128, kSmem>>>(inp, (float*)d_out);
}

// round 6
// speedup vs baseline: 1.6038x; 1.6038x over previous
#include <cuda_runtime.h>

// NT-Xent loss. inp: (C=8, V=2, B=4096, D=512) fp32.
// Block per 4 b's (256 thr), double-buffered cp.async.cg (32KB stages).
// Gram: lane owns one float4 d-chunk (chunk = w*16 + (lane&15)); lane bit4
// picks col half. 8x8 scalar-FMA tile per lane (64 accs), anchors broadcast.
// 4-stage folded butterfly -> lane owns flat64 idx 4*(lane&15)+m (m=0..3),
// one float4 STS into sPart[w]. Odd-col sumsq fused; even norms = Gram diag.
// Epilogue (128 thr): cross-warp sum, norms, masked 16-wide LSE (R2-validated).

static constexpr int      kB    = 4096;
static constexpr int      kIter = 4;
static constexpr int      kGrid = kB / kIter;      // 1024
static constexpr unsigned FULL  = 0xffffffffu;
static constexpr int      kTileF4 = 16 * 128;      // float4 per stage
static constexpr int      kSmem   = 2 * kTileF4 * 16;  // 64 KB dynamic

__device__ float    g_partials[kGrid];
__device__ unsigned g_ticket;   // zero-init; reset by last CTA every launch

__device__ __forceinline__ float elem(const float4& v, int d) {
    return d == 0 ? v.x : d == 1 ? v.y : d == 2 ? v.z : v.w;
}

__global__ void __launch_bounds__(256, 2)
ntxent(const float* __restrict__ inp, float* __restrict__ out)
{
    extern __shared__ float4 Xs[];        // [2][16][128]
    __shared__ float    sPart[8][128];
    __shared__ float    sOdd[8][8];
    __shared__ float    sInv[16];
    __shared__ float    sLoss[8];
    __shared__ unsigned sFlag;

    const int tid   = threadIdx.x;
    const int w     = tid >> 5;
    const int lane  = tid & 31;
    const int h     = lane >> 4;        // col half: k in [8h, 8h+8)
    const int L4    = lane & 15;
    const int chunk = w * 16 + L4;      // this lane's float4 d-chunk

    if (tid < 8) sLoss[tid] = 0.f;

    // cp.async assignment: thread t copies row = t>>4, chunks (t&15)+16m
    const int row = tid >> 4;
    const int c16 = tid & 15;
    const long long b0 = (long long)blockIdx.x * kIter;
    const char* gbase = (const char*)(inp + ((size_t)row * kB + b0) * 512) + c16 * 16;
    unsigned sdst[2];
    sdst[0] = (unsigned)__cvta_generic_to_shared(&Xs[row * 128 + c16]);
    sdst[1] = sdst[0] + kTileF4 * 16;

    auto issue = [&](int it, int buf) {
        const char* g = gbase + (size_t)it * 2048;   // +512 floats per b
        #pragma unroll
        for (int m = 0; m < 8; m++)
            asm volatile("cp.async.cg.shared.global [%0], [%1], 16;"
                         :: "r"(sdst[buf] + m * 256), "l"(g + m * 256));
        asm volatile("cp.async.commit_group;" ::: "memory");
    };

    issue(0, 0);
    issue(1, 1);

    #pragma unroll
    for (int it = 0; it < kIter; it++) {
        const int buf = it & 1;
        if (it < kIter - 1) asm volatile("cp.async.wait_group 1;" ::: "memory");
        else                asm volatile("cp.async.wait_group 0;" ::: "memory");
        __syncthreads();

        const float4* X = Xs + buf * kTileF4;

        // ---- per-lane 8x8 Gram tile + odd-col sumsq ----
        float4 A[8];
        #pragma unroll
        for (int i = 0; i < 8; i++) A[i] = X[(2 * i) * 128 + chunk];

        float a[64];
        #pragma unroll
        for (int q = 0; q < 64; q++) a[q] = 0.f;
        float ssv[4] = {0.f, 0.f, 0.f, 0.f};

        #pragma unroll
        for (int jg = 0; jg < 2; jg++) {
            float4 Cv[4];
            #pragma unroll
            for (int jj = 0; jj < 4; jj++)
                Cv[jj] = X[(8 * h + jg * 4 + jj) * 128 + chunk];
            // odd rows j = jg*4 + {1,3}  ->  ssv[jg*2 + {0,1}]
            #pragma unroll
            for (int o = 0; o < 2; o++) {
                const float4 x = Cv[2 * o + 1];
                float s = ssv[jg * 2 + o];
                s = fmaf(x.x, x.x, fmaf(x.y, x.y, fmaf(x.z, x.z, fmaf(x.w, x.w, s))));
                ssv[jg * 2 + o] = s;
            }
            #pragma unroll
            for (int d = 0; d < 4; d++)
                #pragma unroll
                for (int i = 0; i < 8; i++) {
                    const float av = elem(A[i], d);
                    #pragma unroll
                    for (int jj = 0; jj < 4; jj++)
                        a[i * 8 + jg * 4 + jj] =
                            fmaf(av, elem(Cv[jj], d), a[i * 8 + jg * 4 + jj]);
                }
        }

        // ---- folded butterfly over the 16 chunk-lanes (bits 3..0) ----
        #pragma unroll
        for (int s = 0; s < 4; s++) {
            const int  off = 8 >> s;
            const int  n   = 32 >> s;
            const bool hi  = (lane & off) != 0;
            #pragma unroll
            for (int m = 0; m < n; m++) {
                const float mine = hi ? a[m + n] : a[m];
                const float send = hi ? a[m]     : a[m + n];
                a[m] = mine + __shfl_xor_sync(FULL, send, off);
            }
        }
        // lane owns flat64 = 4*L4 + m: i = L4>>1, k = (L4&1)*4 + m + 8h
        {
            const int i  = L4 >> 1;
            const int kb = (L4 & 1) * 4 + 8 * h;
            *reinterpret_cast<float4*>(&sPart[w][i * 16 + kb]) =
                make_float4(a[0], a[1], a[2], a[3]);
        }
        // odd sumsq: reduce over 16 chunk-lanes
        #pragma unroll
        for (int off = 8; off > 0; off >>= 1)
            #pragma unroll
            for (int q = 0; q < 4; q++)
                ssv[q] += __shfl_xor_sync(FULL, ssv[q], off);
        if (L4 == 0) {
            #pragma unroll
            for (int q = 0; q < 4; q++)
                sOdd[w][q + 4 * h] = ssv[q];     // row 2*(q+4h)+1
        }
        __syncthreads();

        if (it + 2 < kIter) issue(it + 2, buf);

        // ---- epilogue: warps 0-3 ----
        const int ei = tid >> 4;
        const int ek = tid & 15;
        float g = 0.f;
        if (tid < 128) {
            #pragma unroll
            for (int ww = 0; ww < 8; ww++) g += sPart[ww][tid];
            if (ek == 2 * ei) sInv[ek] = 1.f / fmaxf(sqrtf(g), 1e-12f);
            if (tid < 8) {
                float so = 0.f;
                #pragma unroll
                for (int ww = 0; ww < 8; ww++) so += sOdd[ww][tid];
                sInv[2 * tid + 1] = 1.f / fmaxf(sqrtf(so), 1e-12f);
            }
        }
        __syncthreads();
        if (tid < 128) {
            const float sim   = g * sInv[2 * ei] * sInv[ek] * 10.f;
            const bool  valid = ((ek >> 1) != ei) || (ek == 2 * ei + 1);
            float mx = valid ? sim : -1e30f;
            #pragma unroll
            for (int off = 8; off > 0; off >>= 1)
                mx = fmaxf(mx, __shfl_xor_sync(FULL, mx, off, 16));
            float e = valid ? __expf(sim - mx) : 0.f;
            #pragma unroll
            for (int off = 8; off > 0; off >>= 1)
                e += __shfl_xor_sync(FULL, e, off, 16);
            if (ek == 2 * ei + 1)
                sLoss[ei] += (mx + __logf(e)) - sim;
        }
        __syncthreads();
    }

    // ---- deterministic fused finish ----
    if (tid == 0) {
        float t = 0.f;
        #pragma unroll
        for (int i = 0; i < 8; i++) t += sLoss[i];
        g_partials[blockIdx.x] = t;
        __threadfence();
        const unsigned tk = atomicAdd(&g_ticket, 1u);
        sFlag = (tk == kGrid - 1) ? 1u : 0u;
    }
    __syncthreads();
    if (sFlag) {
        float s = 0.f;
        #pragma unroll
        for (int m = 0; m < kGrid / 256; m++)
            s += __ldcg(&g_partials[tid + m * 256]);   // fixed order
        #pragma unroll
        for (int off = 16; off > 0; off >>= 1)
            s += __shfl_xor_sync(FULL, s, off);
        if (lane == 0) sPart[0][w] = s;
        __syncthreads();
        if (tid == 0) {
            float tot = 0.f;
            #pragma unroll
            for (int i = 0; i < 8; i++) tot += sPart[0][i];
            out[0] = tot * (1.0f / (8.0f * 4096.0f));
            g_ticket = 0u;   // reset for next graph replay
        }
    }
}

extern "C" void kernel_launch(void* const* d_in, const int* in_sizes, int n_in,
                              void* d_out, int out_size) {
    (void)in_sizes; (void)n_in; (void)out_size;
    const float* inp = (const float*)d_in[0];
    cudaFuncSetAttribute(ntxent, cudaFuncAttributeMaxDynamicSharedMemorySize, kSmem);
    ntxent<<<kGrid, 256, kSmem>>>(inp, (float*)d_out);
}